// round 14
// baseline (speedup 1.0000x reference)
#include <cuda_runtime.h>
#include <cuda_fp16.h>
#include <cstdint>

// ============================================================================
// Problem sizes / tiling
// ============================================================================
#define MM 8192
#define NN 16384
#define KK 4096
#define BM 128
#define BN 256
#define BKB 64                  // K-bytes per stage tile = 32 fp16 elements
#define STAGES 4
#define KTILES (KK * 2 / BKB)   // 128
#define ROWB 80                 // padded SMEM row: 64 data bytes + 16 pad (conflict-free)
#define ATILE_A (BM * ROWB)     // 10240 bytes (A tile)
#define ATILE_W (BN * ROWB)     // 20480 bytes (W tile)
#define STAGE_BYTES (ATILE_A + ATILE_W)    // 30720
#define SMEM_BYTES (STAGES * STAGE_BYTES)  // 122880
#define NTHREADS 256

// Scratch (allocation-free rule: __device__ globals)
static __device__ __align__(1024) __half g_A[(size_t)MM * KK];   // 64 MB  fp16 x
static __device__ __align__(1024) __half g_Wh[(size_t)NN * KK];  // 128 MB fp16 weights

// ============================================================================
// PTX helpers (plain sm_103-safe)
// ============================================================================
__device__ __forceinline__ uint32_t smem_to_u32(const void* p) {
    uint32_t a;
    asm("{ .reg .u64 t; cvta.to.shared.u64 t, %1; cvt.u32.u64 %0, t; }" : "=r"(a) : "l"(p));
    return a;
}

__device__ __forceinline__ void cp16(uint32_t dst, const void* src) {
    asm volatile("cp.async.cg.shared.global [%0], [%1], 16;" :: "r"(dst), "l"(src));
}
#define CP_COMMIT() asm volatile("cp.async.commit_group;" ::: "memory")
#define CP_WAIT(n)  asm volatile("cp.async.wait_group %0;" :: "n"(n) : "memory")

__device__ __forceinline__ void ldm4(uint32_t* r, uint32_t addr) {
    asm volatile("ldmatrix.sync.aligned.m8n8.x4.shared.b16 {%0,%1,%2,%3}, [%4];"
        : "=r"(r[0]), "=r"(r[1]), "=r"(r[2]), "=r"(r[3]) : "r"(addr));
}

// D(f32) += A(f16,row) * B(f16,col);  m16n8k16  (validated choreography)
__device__ __forceinline__ void mma_f16(float* d, const uint32_t* a, uint32_t b0, uint32_t b1) {
    asm volatile(
        "mma.sync.aligned.m16n8k16.row.col.f32.f16.f16.f32 "
        "{%0,%1,%2,%3}, {%4,%5,%6,%7}, {%8,%9}, {%0,%1,%2,%3};"
        : "+f"(d[0]), "+f"(d[1]), "+f"(d[2]), "+f"(d[3])
        : "r"(a[0]), "r"(a[1]), "r"(a[2]), "r"(a[3]), "r"(b0), "r"(b1));
}

// ============================================================================
// W convert: int32-stored int8 weights -> fp16 (exact for |w| <= 2048).
// ============================================================================
__global__ void __launch_bounds__(256) k_wconv(const int4* __restrict__ w32) {
    size_t i = (size_t)blockIdx.x * blockDim.x + threadIdx.x;   // 0 .. 8388607
    int4 v0 = w32[i * 2 + 0];
    int4 v1 = w32[i * 2 + 1];
    uint32_t p[4];
    p[0] = (uint32_t)__half_as_ushort(__float2half_rn((float)v0.x)) |
           ((uint32_t)__half_as_ushort(__float2half_rn((float)v0.y)) << 16);
    p[1] = (uint32_t)__half_as_ushort(__float2half_rn((float)v0.z)) |
           ((uint32_t)__half_as_ushort(__float2half_rn((float)v0.w)) << 16);
    p[2] = (uint32_t)__half_as_ushort(__float2half_rn((float)v1.x)) |
           ((uint32_t)__half_as_ushort(__float2half_rn((float)v1.y)) << 16);
    p[3] = (uint32_t)__half_as_ushort(__float2half_rn((float)v1.z)) |
           ((uint32_t)__half_as_ushort(__float2half_rn((float)v1.w)) << 16);
    *(uint4*)((char*)g_Wh + i * 16) = make_uint4(p[0], p[1], p[2], p[3]);
}

// ============================================================================
// x convert: f32 -> fp16 (rel rounding RMS ~3e-4, within 1e-3 budget).
// ============================================================================
__global__ void __launch_bounds__(256) k_xconv(const float4* __restrict__ x) {
    size_t i = (size_t)blockIdx.x * blockDim.x + threadIdx.x;   // 0 .. 8388607
    float4 v = x[i];
    uint2 H;
    H.x = (uint32_t)__half_as_ushort(__float2half_rn(v.x)) |
          ((uint32_t)__half_as_ushort(__float2half_rn(v.y)) << 16);
    H.y = (uint32_t)__half_as_ushort(__float2half_rn(v.z)) |
          ((uint32_t)__half_as_ushort(__float2half_rn(v.w)) << 16);
    *(uint2*)((char*)g_A + i * 8) = H;
}

// ============================================================================
// GEMM: acc(f32) = A @ Wh^T ;  out = acc * scale_n + bias_n
// Block 128x256, 8 warps (2m x 4n), warp tile 64x64, 4-stage cp.async.
// 256 threads -> 255-reg ceiling; acc=128 + frags + idx ~ 195 regs, no spill.
// Fragment smem reads drop 96KB -> 64KB per kt (register-level reuse 2x).
// ============================================================================
__global__ void __launch_bounds__(NTHREADS, 1) gemm_kernel(
    const float* __restrict__ scale,   // [NN]
    const float* __restrict__ bias,    // [NN]
    float* __restrict__ out)           // [MM][NN]
{
    extern __shared__ char smem[];
    uint32_t sb = smem_to_u32(smem);
    int tid = threadIdx.x;

    // L2-friendly tile order: groups of 8 m-tiles sweep n
    const int ntm = MM / BM, ntn = NN / BN;   // 64, 64
    const int GROUPM = 8;
    int pid = blockIdx.x;
    int npg = GROUPM * ntn;
    int gid = pid / npg;
    int fm = gid * GROUPM;
    int gsz = (ntm - fm < GROUPM) ? (ntm - fm) : GROUPM;
    int tm = fm + (pid % gsz);
    int tn = (pid % npg) / gsz;
    int m0 = tm * BM, n0 = tn * BN;

    const char* pA = (const char*)g_A;
    const char* pW = (const char*)g_Wh;
    const size_t RB = (size_t)KK * 2;        // bytes per logical row

    // ---- stage loader: (512 A + 1024 W) x 16B chunks / 256 threads = 6 ----
    auto load_stage = [&](int slot, int kt) {
        uint32_t sbase = sb + slot * STAGE_BYTES;
        size_t k0 = (size_t)kt * BKB;
#pragma unroll
        for (int i = 0; i < 6; i++) {
            int c = tid + i * NTHREADS;      // 0..1535
            if (c < 512) {
                int row = c >> 2, ch = c & 3;
                cp16(sbase + row * ROWB + ch * 16,
                     pA + (size_t)(m0 + row) * RB + k0 + ch * 16);
            } else {
                int cw = c - 512;
                int row = cw >> 2, ch = cw & 3;
                cp16(sbase + ATILE_A + row * ROWB + ch * 16,
                     pW + (size_t)(n0 + row) * RB + k0 + ch * 16);
            }
        }
    };

    int w = tid >> 5, lane = tid & 31;
    int mw = w >> 2, nw = w & 3;             // warp grid 2m x 4n, warp tile 64x64
    int r = lane & 7, seg = lane >> 3;
    int g = lane >> 2, q = lane & 3;         // C-fragment coords

    // ldmatrix source offsets — validated choreography (R6/R8/R10/R11/R13)
    uint32_t aoff[4];
#pragma unroll
    for (int mf = 0; mf < 4; mf++) {
        int arow = mw * 64 + mf * 16 + r + (seg & 1) * 8;
        aoff[mf] = (uint32_t)arow * ROWB + (seg >> 1) * 16;
    }
    uint32_t boff[4];
#pragma unroll
    for (int p = 0; p < 4; p++) {
        int brow = nw * 64 + p * 16 + r + (seg >> 1) * 8;
        boff[p] = ATILE_A + (uint32_t)brow * ROWB + (seg & 1) * 16;
    }

    float acc[4][8][4] = {};   // [m16 frag][n8 frag][c0..c3] = 128 regs

    // ---- prologue ----
#pragma unroll
    for (int s = 0; s < STAGES - 1; s++) { load_stage(s, s); CP_COMMIT(); }

    // ---- mainloop ----
    for (int kt = 0; kt < KTILES; kt++) {
        CP_WAIT(STAGES - 2);
        __syncthreads();
        if (kt + STAGES - 1 < KTILES) load_stage((kt + STAGES - 1) % STAGES, kt + STAGES - 1);
        CP_COMMIT();

        uint32_t sbase = sb + (kt % STAGES) * STAGE_BYTES;
#pragma unroll
        for (int ks = 0; ks < 2; ks++) {     // 2 x 32B = 2 x k16 per tile
            uint32_t fa[4][4], fB[4][4];
#pragma unroll
            for (int mf = 0; mf < 4; mf++) ldm4(fa[mf], sbase + aoff[mf] + ks * 32);
#pragma unroll
            for (int p = 0; p < 4; p++)    ldm4(fB[p], sbase + boff[p] + ks * 32);
#pragma unroll
            for (int mf = 0; mf < 4; mf++) {
#pragma unroll
                for (int nf = 0; nf < 8; nf++) {
                    uint32_t b0 = fB[nf >> 1][(nf & 1) * 2];
                    uint32_t b1 = fB[nf >> 1][(nf & 1) * 2 + 1];
                    mma_f16(acc[mf][nf], fa[mf], b0, b1);
                }
            }
        }
    }

    // ---- epilogue: out = acc * scale_n + bias_n ----
    // C frag: c0:(g, 2q) c1:(g, 2q+1) c2:(g+8, 2q) c3:(g+8, 2q+1)
#pragma unroll
    for (int mf = 0; mf < 4; mf++) {
        int r0 = m0 + mw * 64 + mf * 16 + g;
#pragma unroll
        for (int nf = 0; nf < 8; nf++) {
            int c = n0 + nw * 64 + nf * 8 + q * 2;
            float sc0 = __ldg(scale + c), sc1 = __ldg(scale + c + 1);
            float bb0 = __ldg(bias + c),  bb1 = __ldg(bias + c + 1);
            const float* d = acc[mf][nf];
            float2 v0 = make_float2(fmaf(d[0], sc0, bb0), fmaf(d[1], sc1, bb1));
            float2 v1 = make_float2(fmaf(d[2], sc0, bb0), fmaf(d[3], sc1, bb1));
            *(float2*)(out + (size_t)r0 * NN + c)       = v0;
            *(float2*)(out + (size_t)(r0 + 8) * NN + c) = v1;
        }
    }
}

// ============================================================================
// Host side — inputs identified by element count
// ============================================================================
extern "C" void kernel_launch(void* const* d_in, const int* in_sizes, int n_in,
                              void* d_out, int out_size) {
    const float*   x     = nullptr;
    const int32_t* w32   = nullptr;
    const float*   scale = nullptr;
    const float*   bias  = nullptr;
    for (int i = 0; i < n_in; i++) {
        if (in_sizes[i] == MM * KK)           x   = (const float*)d_in[i];
        else if (in_sizes[i] == NN * KK)      w32 = (const int32_t*)d_in[i];
        else if (in_sizes[i] == NN) {
            if (!scale) scale = (const float*)d_in[i];
            else        bias  = (const float*)d_in[i];
        }
    }
    float* out = (float*)d_out;

    cudaFuncSetAttribute(gemm_kernel, cudaFuncAttributeMaxDynamicSharedMemorySize, SMEM_BYTES);

    k_wconv<<<(NN * (size_t)KK) / (8 * 256), 256>>>((const int4*)w32);
    k_xconv<<<(MM * (size_t)KK) / (4 * 256), 256>>>((const float4*)x);
    gemm_kernel<<<(MM / BM) * (NN / BN), NTHREADS, SMEM_BYTES>>>(scale, bias, out);
}

// round 15
// speedup vs baseline: 1.1106x; 1.1106x over previous
#include <cuda_runtime.h>
#include <cuda_fp16.h>
#include <cstdint>

// ============================================================================
// Problem sizes / tiling
// ============================================================================
#define MM 8192
#define NN 16384
#define KK 4096
#define BM 128
#define BN 128
#define BKB 64                  // K-bytes per stage tile = 32 fp16 elements
#define STAGES 4
#define KTILES (KK * 2 / BKB)   // 128
#define ROWB 80                 // padded SMEM row: 64 data bytes + 16 pad (conflict-free)
#define ATILE_A (BM * ROWB)     // 10240
#define ATILE_W (BN * ROWB)     // 10240
#define STAGE_BYTES (ATILE_A + ATILE_W)    // 20480
#define SMEM_BYTES (STAGES * STAGE_BYTES)  // 81920  (x2 CTAs = 160KB/SM)
#define NTHREADS 256

// Scratch (allocation-free rule: __device__ globals)
static __device__ __align__(1024) __half g_A[(size_t)MM * KK];   // 64 MB  fp16 x
static __device__ __align__(1024) __half g_Wh[(size_t)NN * KK];  // 128 MB fp16 weights

// ============================================================================
// PTX helpers (plain sm_103-safe)
// ============================================================================
__device__ __forceinline__ uint32_t smem_to_u32(const void* p) {
    uint32_t a;
    asm("{ .reg .u64 t; cvta.to.shared.u64 t, %1; cvt.u32.u64 %0, t; }" : "=r"(a) : "l"(p));
    return a;
}

__device__ __forceinline__ void cp16(uint32_t dst, const void* src) {
    asm volatile("cp.async.cg.shared.global [%0], [%1], 16;" :: "r"(dst), "l"(src));
}
#define CP_COMMIT() asm volatile("cp.async.commit_group;" ::: "memory")
#define CP_WAIT(n)  asm volatile("cp.async.wait_group %0;" :: "n"(n) : "memory")

__device__ __forceinline__ void ldm4(uint32_t* r, uint32_t addr) {
    asm volatile("ldmatrix.sync.aligned.m8n8.x4.shared.b16 {%0,%1,%2,%3}, [%4];"
        : "=r"(r[0]), "=r"(r[1]), "=r"(r[2]), "=r"(r[3]) : "r"(addr));
}

// D(f32) += A(f16,row) * B(f16,col);  m16n8k16  (validated choreography)
__device__ __forceinline__ void mma_f16(float* d, const uint32_t* a, uint32_t b0, uint32_t b1) {
    asm volatile(
        "mma.sync.aligned.m16n8k16.row.col.f32.f16.f16.f32 "
        "{%0,%1,%2,%3}, {%4,%5,%6,%7}, {%8,%9}, {%0,%1,%2,%3};"
        : "+f"(d[0]), "+f"(d[1]), "+f"(d[2]), "+f"(d[3])
        : "r"(a[0]), "r"(a[1]), "r"(a[2]), "r"(a[3]), "r"(b0), "r"(b1));
}

// ============================================================================
// W convert: int32-stored int8 weights -> fp16 (exact for |w| <= 2048).
// ============================================================================
__global__ void __launch_bounds__(256) k_wconv(const int4* __restrict__ w32) {
    size_t i = (size_t)blockIdx.x * blockDim.x + threadIdx.x;   // 0 .. 8388607
    int4 v0 = w32[i * 2 + 0];
    int4 v1 = w32[i * 2 + 1];
    uint32_t p[4];
    p[0] = (uint32_t)__half_as_ushort(__float2half_rn((float)v0.x)) |
           ((uint32_t)__half_as_ushort(__float2half_rn((float)v0.y)) << 16);
    p[1] = (uint32_t)__half_as_ushort(__float2half_rn((float)v0.z)) |
           ((uint32_t)__half_as_ushort(__float2half_rn((float)v0.w)) << 16);
    p[2] = (uint32_t)__half_as_ushort(__float2half_rn((float)v1.x)) |
           ((uint32_t)__half_as_ushort(__float2half_rn((float)v1.y)) << 16);
    p[3] = (uint32_t)__half_as_ushort(__float2half_rn((float)v1.z)) |
           ((uint32_t)__half_as_ushort(__float2half_rn((float)v1.w)) << 16);
    *(uint4*)((char*)g_Wh + i * 16) = make_uint4(p[0], p[1], p[2], p[3]);
}

// ============================================================================
// x convert: f32 -> fp16 (rel rounding RMS ~3e-4, within 1e-3 budget).
// ============================================================================
__global__ void __launch_bounds__(256) k_xconv(const float4* __restrict__ x) {
    size_t i = (size_t)blockIdx.x * blockDim.x + threadIdx.x;   // 0 .. 8388607
    float4 v = x[i];
    uint2 H;
    H.x = (uint32_t)__half_as_ushort(__float2half_rn(v.x)) |
          ((uint32_t)__half_as_ushort(__float2half_rn(v.y)) << 16);
    H.y = (uint32_t)__half_as_ushort(__float2half_rn(v.z)) |
          ((uint32_t)__half_as_ushort(__float2half_rn(v.w)) << 16);
    *(uint2*)((char*)g_A + i * 8) = H;
}

// ============================================================================
// GEMM: acc(f32) = A @ Wh^T ;  out = acc * scale_n + bias_n
// Block 128x128, 8 warps (2m x 4n), warp tile 64x32, 4-stage cp.async.
// 2 CTAs/SM (launch_bounds(256,2)) -> 16 warps/SM with 30% less L1-port
// traffic per output than R13's single-CTA config.
// ============================================================================
__global__ void __launch_bounds__(NTHREADS, 2) gemm_kernel(
    const float* __restrict__ scale,   // [NN]
    const float* __restrict__ bias,    // [NN]
    float* __restrict__ out)           // [MM][NN]
{
    extern __shared__ char smem[];
    uint32_t sb = smem_to_u32(smem);
    int tid = threadIdx.x;

    // L2-friendly tile order: groups of 16 m-tiles sweep n
    const int ntm = MM / BM, ntn = NN / BN;   // 64, 128
    const int GROUPM = 16;
    int pid = blockIdx.x;
    int npg = GROUPM * ntn;
    int gid = pid / npg;
    int fm = gid * GROUPM;
    int gsz = (ntm - fm < GROUPM) ? (ntm - fm) : GROUPM;
    int tm = fm + (pid % gsz);
    int tn = (pid % npg) / gsz;
    int m0 = tm * BM, n0 = tn * BN;

    const char* pA = (const char*)g_A;
    const char* pW = (const char*)g_Wh;
    const size_t RB = (size_t)KK * 2;        // bytes per logical row

    // ---- stage loader: (512 A + 512 W) x 16B chunks / 256 threads = 4 ----
    auto load_stage = [&](int slot, int kt) {
        uint32_t sbase = sb + slot * STAGE_BYTES;
        size_t k0 = (size_t)kt * BKB;
#pragma unroll
        for (int i = 0; i < 4; i++) {
            int c = tid + i * NTHREADS;      // 0..1023
            if (c < 512) {
                int row = c >> 2, ch = c & 3;
                cp16(sbase + row * ROWB + ch * 16,
                     pA + (size_t)(m0 + row) * RB + k0 + ch * 16);
            } else {
                int cw = c - 512;
                int row = cw >> 2, ch = cw & 3;
                cp16(sbase + ATILE_A + row * ROWB + ch * 16,
                     pW + (size_t)(n0 + row) * RB + k0 + ch * 16);
            }
        }
    };

    int w = tid >> 5, lane = tid & 31;
    int mw = w >> 2, nw = w & 3;             // warp grid 2m x 4n, warp tile 64x32
    int r = lane & 7, seg = lane >> 3;
    int g = lane >> 2, q = lane & 3;         // C-fragment coords

    // ldmatrix source offsets — validated choreography
    uint32_t aoff[4];
#pragma unroll
    for (int mf = 0; mf < 4; mf++) {
        int arow = mw * 64 + mf * 16 + r + (seg & 1) * 8;
        aoff[mf] = (uint32_t)arow * ROWB + (seg >> 1) * 16;
    }
    uint32_t boff[2];
#pragma unroll
    for (int p = 0; p < 2; p++) {
        int brow = nw * 32 + p * 16 + r + (seg >> 1) * 8;
        boff[p] = ATILE_A + (uint32_t)brow * ROWB + (seg & 1) * 16;
    }

    float acc[4][4][4] = {};   // [m16 frag][n8 frag][c0..c3] = 64 regs

    // ---- prologue ----
#pragma unroll
    for (int s = 0; s < STAGES - 1; s++) { load_stage(s, s); CP_COMMIT(); }

    // ---- mainloop ----
    for (int kt = 0; kt < KTILES; kt++) {
        CP_WAIT(STAGES - 2);
        __syncthreads();
        if (kt + STAGES - 1 < KTILES) load_stage((kt + STAGES - 1) % STAGES, kt + STAGES - 1);
        CP_COMMIT();

        uint32_t sbase = sb + (kt % STAGES) * STAGE_BYTES;
#pragma unroll
        for (int ks = 0; ks < 2; ks++) {     // 2 x 32B = 2 x k16 per tile
            uint32_t fa[4][4], fB[2][4];
#pragma unroll
            for (int mf = 0; mf < 4; mf++) ldm4(fa[mf], sbase + aoff[mf] + ks * 32);
#pragma unroll
            for (int p = 0; p < 2; p++)    ldm4(fB[p], sbase + boff[p] + ks * 32);
#pragma unroll
            for (int mf = 0; mf < 4; mf++) {
#pragma unroll
                for (int nf = 0; nf < 4; nf++) {
                    uint32_t b0 = fB[nf >> 1][(nf & 1) * 2];
                    uint32_t b1 = fB[nf >> 1][(nf & 1) * 2 + 1];
                    mma_f16(acc[mf][nf], fa[mf], b0, b1);
                }
            }
        }
    }

    // ---- epilogue: out = acc * scale_n + bias_n ----
    // C frag: c0:(g, 2q) c1:(g, 2q+1) c2:(g+8, 2q) c3:(g+8, 2q+1)
#pragma unroll
    for (int mf = 0; mf < 4; mf++) {
        int r0 = m0 + mw * 64 + mf * 16 + g;
#pragma unroll
        for (int nf = 0; nf < 4; nf++) {
            int c = n0 + nw * 32 + nf * 8 + q * 2;
            float sc0 = __ldg(scale + c), sc1 = __ldg(scale + c + 1);
            float bb0 = __ldg(bias + c),  bb1 = __ldg(bias + c + 1);
            const float* d = acc[mf][nf];
            float2 v0 = make_float2(fmaf(d[0], sc0, bb0), fmaf(d[1], sc1, bb1));
            float2 v1 = make_float2(fmaf(d[2], sc0, bb0), fmaf(d[3], sc1, bb1));
            *(float2*)(out + (size_t)r0 * NN + c)       = v0;
            *(float2*)(out + (size_t)(r0 + 8) * NN + c) = v1;
        }
    }
}

// ============================================================================
// Host side — inputs identified by element count
// ============================================================================
extern "C" void kernel_launch(void* const* d_in, const int* in_sizes, int n_in,
                              void* d_out, int out_size) {
    const float*   x     = nullptr;
    const int32_t* w32   = nullptr;
    const float*   scale = nullptr;
    const float*   bias  = nullptr;
    for (int i = 0; i < n_in; i++) {
        if (in_sizes[i] == MM * KK)           x   = (const float*)d_in[i];
        else if (in_sizes[i] == NN * KK)      w32 = (const int32_t*)d_in[i];
        else if (in_sizes[i] == NN) {
            if (!scale) scale = (const float*)d_in[i];
            else        bias  = (const float*)d_in[i];
        }
    }
    float* out = (float*)d_out;

    cudaFuncSetAttribute(gemm_kernel, cudaFuncAttributeMaxDynamicSharedMemorySize, SMEM_BYTES);

    k_wconv<<<(NN * (size_t)KK) / (8 * 256), 256>>>((const int4*)w32);
    k_xconv<<<(MM * (size_t)KK) / (4 * 256), 256>>>((const float4*)x);
    gemm_kernel<<<(MM / BM) * (NN / BN), NTHREADS, SMEM_BYTES>>>(scale, bias, out);
}

// round 16
// speedup vs baseline: 1.2117x; 1.0911x over previous
#include <cuda_runtime.h>
#include <cuda_fp16.h>
#include <cstdint>

// ============================================================================
// Problem sizes / tiling
// ============================================================================
#define MM 8192
#define NN 16384
#define KK 4096
#define BM 128
#define BN 256
#define BKB 128                 // K-bytes per stage tile = 64 fp16 elements
#define STAGES 3
#define KTILES (KK * 2 / BKB)   // 64
#define ROWB 144                // padded SMEM row: 128 data bytes + 16 pad (conflict-free)
#define ATILE_A (BM * ROWB)     // 18432
#define ATILE_W (BN * ROWB)     // 36864
#define STAGE_BYTES (ATILE_A + ATILE_W)    // 55296
#define SMEM_BYTES (STAGES * STAGE_BYTES)  // 165888
#define NTHREADS 512

// Scratch (allocation-free rule: __device__ globals)
static __device__ __align__(1024) __half g_A[(size_t)MM * KK];   // 64 MB  fp16 x
static __device__ __align__(1024) __half g_Wh[(size_t)NN * KK];  // 128 MB fp16 weights

// ============================================================================
// PTX helpers (plain sm_103-safe)
// ============================================================================
__device__ __forceinline__ uint32_t smem_to_u32(const void* p) {
    uint32_t a;
    asm("{ .reg .u64 t; cvta.to.shared.u64 t, %1; cvt.u32.u64 %0, t; }" : "=r"(a) : "l"(p));
    return a;
}

__device__ __forceinline__ void cp16(uint32_t dst, const void* src) {
    asm volatile("cp.async.cg.shared.global [%0], [%1], 16;" :: "r"(dst), "l"(src));
}
#define CP_COMMIT() asm volatile("cp.async.commit_group;" ::: "memory")
#define CP_WAIT(n)  asm volatile("cp.async.wait_group %0;" :: "n"(n) : "memory")

__device__ __forceinline__ void ldm4(uint32_t* r, uint32_t addr) {
    asm volatile("ldmatrix.sync.aligned.m8n8.x4.shared.b16 {%0,%1,%2,%3}, [%4];"
        : "=r"(r[0]), "=r"(r[1]), "=r"(r[2]), "=r"(r[3]) : "r"(addr));
}

// D(f32) += A(f16,row) * B(f16,col);  m16n8k16  (validated choreography)
__device__ __forceinline__ void mma_f16(float* d, const uint32_t* a, uint32_t b0, uint32_t b1) {
    asm volatile(
        "mma.sync.aligned.m16n8k16.row.col.f32.f16.f16.f32 "
        "{%0,%1,%2,%3}, {%4,%5,%6,%7}, {%8,%9}, {%0,%1,%2,%3};"
        : "+f"(d[0]), "+f"(d[1]), "+f"(d[2]), "+f"(d[3])
        : "r"(a[0]), "r"(a[1]), "r"(a[2]), "r"(a[3]), "r"(b0), "r"(b1));
}

// ============================================================================
// W convert: int32-stored int8 weights -> fp16 (exact for |w| <= 2048).
// ============================================================================
__global__ void __launch_bounds__(256) k_wconv(const int4* __restrict__ w32) {
    size_t i = (size_t)blockIdx.x * blockDim.x + threadIdx.x;   // 0 .. 8388607
    int4 v0 = w32[i * 2 + 0];
    int4 v1 = w32[i * 2 + 1];
    uint32_t p[4];
    p[0] = (uint32_t)__half_as_ushort(__float2half_rn((float)v0.x)) |
           ((uint32_t)__half_as_ushort(__float2half_rn((float)v0.y)) << 16);
    p[1] = (uint32_t)__half_as_ushort(__float2half_rn((float)v0.z)) |
           ((uint32_t)__half_as_ushort(__float2half_rn((float)v0.w)) << 16);
    p[2] = (uint32_t)__half_as_ushort(__float2half_rn((float)v1.x)) |
           ((uint32_t)__half_as_ushort(__float2half_rn((float)v1.y)) << 16);
    p[3] = (uint32_t)__half_as_ushort(__float2half_rn((float)v1.z)) |
           ((uint32_t)__half_as_ushort(__float2half_rn((float)v1.w)) << 16);
    *(uint4*)((char*)g_Wh + i * 16) = make_uint4(p[0], p[1], p[2], p[3]);
}

// ============================================================================
// x convert: f32 -> fp16 (rel rounding RMS ~3e-4, within 1e-3 budget).
// ============================================================================
__global__ void __launch_bounds__(256) k_xconv(const float4* __restrict__ x) {
    size_t i = (size_t)blockIdx.x * blockDim.x + threadIdx.x;   // 0 .. 8388607
    float4 v = x[i];
    uint2 H;
    H.x = (uint32_t)__half_as_ushort(__float2half_rn(v.x)) |
          ((uint32_t)__half_as_ushort(__float2half_rn(v.y)) << 16);
    H.y = (uint32_t)__half_as_ushort(__float2half_rn(v.z)) |
          ((uint32_t)__half_as_ushort(__float2half_rn(v.w)) << 16);
    *(uint2*)((char*)g_A + i * 8) = H;
}

// ============================================================================
// GEMM: acc(f32) = A @ Wh^T ;  out = acc * scale_n + bias_n
// Block 128x256, 16 warps (4m x 4n), warp tile 32x64, BKB=128, 3-stage.
// Halved k-iteration count amortizes per-kt sync/drain overhead (~580 cyc).
// ============================================================================
__global__ void __launch_bounds__(NTHREADS, 1) gemm_kernel(
    const float* __restrict__ scale,   // [NN]
    const float* __restrict__ bias,    // [NN]
    float* __restrict__ out)           // [MM][NN]
{
    extern __shared__ char smem[];
    uint32_t sb = smem_to_u32(smem);
    int tid = threadIdx.x;

    // L2-friendly tile order: groups of 8 m-tiles sweep n
    const int ntm = MM / BM, ntn = NN / BN;   // 64, 64
    const int GROUPM = 8;
    int pid = blockIdx.x;
    int npg = GROUPM * ntn;
    int gid = pid / npg;
    int fm = gid * GROUPM;
    int gsz = (ntm - fm < GROUPM) ? (ntm - fm) : GROUPM;
    int tm = fm + (pid % gsz);
    int tn = (pid % npg) / gsz;
    int m0 = tm * BM, n0 = tn * BN;

    const char* pA = (const char*)g_A;
    const char* pW = (const char*)g_Wh;
    const size_t RB = (size_t)KK * 2;        // bytes per logical row

    // ---- stage loader: (1024 A + 2048 W) x 16B chunks / 512 threads = 6 ----
    auto load_stage = [&](int slot, int kt) {
        uint32_t sbase = sb + slot * STAGE_BYTES;
        size_t k0 = (size_t)kt * BKB;
#pragma unroll
        for (int i = 0; i < 6; i++) {
            int c = tid + i * NTHREADS;      // 0..3071
            if (c < 1024) {
                int row = c >> 3, ch = c & 7;
                cp16(sbase + row * ROWB + ch * 16,
                     pA + (size_t)(m0 + row) * RB + k0 + ch * 16);
            } else {
                int cw = c - 1024;
                int row = cw >> 3, ch = cw & 7;
                cp16(sbase + ATILE_A + row * ROWB + ch * 16,
                     pW + (size_t)(n0 + row) * RB + k0 + ch * 16);
            }
        }
    };

    int w = tid >> 5, lane = tid & 31;
    int mw = w >> 2, nw = w & 3;             // warp grid 4m x 4n, warp tile 32x64
    int r = lane & 7, seg = lane >> 3;
    int g = lane >> 2, q = lane & 3;         // C-fragment coords

    // ldmatrix source offsets — validated choreography (R6..R15)
    uint32_t aoff[2];
#pragma unroll
    for (int mf = 0; mf < 2; mf++) {
        int arow = mw * 32 + mf * 16 + r + (seg & 1) * 8;
        aoff[mf] = (uint32_t)arow * ROWB + (seg >> 1) * 16;
    }
    uint32_t boff[4];
#pragma unroll
    for (int p = 0; p < 4; p++) {
        int brow = nw * 64 + p * 16 + r + (seg >> 1) * 8;
        boff[p] = ATILE_A + (uint32_t)brow * ROWB + (seg & 1) * 16;
    }

    float acc[2][8][4] = {};   // [m16 frag][n8 frag][c0..c3] = 64 regs

    // ---- prologue ----
#pragma unroll
    for (int s = 0; s < STAGES - 1; s++) { load_stage(s, s); CP_COMMIT(); }

    // ---- mainloop ----
    for (int kt = 0; kt < KTILES; kt++) {
        CP_WAIT(STAGES - 2);
        __syncthreads();
        if (kt + STAGES - 1 < KTILES) load_stage((kt + STAGES - 1) % STAGES, kt + STAGES - 1);
        CP_COMMIT();

        uint32_t sbase = sb + (kt % STAGES) * STAGE_BYTES;
#pragma unroll
        for (int ks = 0; ks < 4; ks++) {     // 4 x 32B = 4 x k16 per tile
            uint32_t fa[2][4], fB[4][4];
#pragma unroll
            for (int mf = 0; mf < 2; mf++) ldm4(fa[mf], sbase + aoff[mf] + ks * 32);
#pragma unroll
            for (int p = 0; p < 4; p++)    ldm4(fB[p], sbase + boff[p] + ks * 32);
#pragma unroll
            for (int mf = 0; mf < 2; mf++) {
#pragma unroll
                for (int nf = 0; nf < 8; nf++) {
                    uint32_t b0 = fB[nf >> 1][(nf & 1) * 2];
                    uint32_t b1 = fB[nf >> 1][(nf & 1) * 2 + 1];
                    mma_f16(acc[mf][nf], fa[mf], b0, b1);
                }
            }
        }
    }

    // ---- epilogue: out = acc * scale_n + bias_n ----
    // C frag: c0:(g, 2q) c1:(g, 2q+1) c2:(g+8, 2q) c3:(g+8, 2q+1)
#pragma unroll
    for (int mf = 0; mf < 2; mf++) {
        int r0 = m0 + mw * 32 + mf * 16 + g;
#pragma unroll
        for (int nf = 0; nf < 8; nf++) {
            int c = n0 + nw * 64 + nf * 8 + q * 2;
            float sc0 = __ldg(scale + c), sc1 = __ldg(scale + c + 1);
            float bb0 = __ldg(bias + c),  bb1 = __ldg(bias + c + 1);
            const float* d = acc[mf][nf];
            float2 v0 = make_float2(fmaf(d[0], sc0, bb0), fmaf(d[1], sc1, bb1));
            float2 v1 = make_float2(fmaf(d[2], sc0, bb0), fmaf(d[3], sc1, bb1));
            *(float2*)(out + (size_t)r0 * NN + c)       = v0;
            *(float2*)(out + (size_t)(r0 + 8) * NN + c) = v1;
        }
    }
}

// ============================================================================
// Host side — inputs identified by element count
// ============================================================================
extern "C" void kernel_launch(void* const* d_in, const int* in_sizes, int n_in,
                              void* d_out, int out_size) {
    const float*   x     = nullptr;
    const int32_t* w32   = nullptr;
    const float*   scale = nullptr;
    const float*   bias  = nullptr;
    for (int i = 0; i < n_in; i++) {
        if (in_sizes[i] == MM * KK)           x   = (const float*)d_in[i];
        else if (in_sizes[i] == NN * KK)      w32 = (const int32_t*)d_in[i];
        else if (in_sizes[i] == NN) {
            if (!scale) scale = (const float*)d_in[i];
            else        bias  = (const float*)d_in[i];
        }
    }
    float* out = (float*)d_out;

    cudaFuncSetAttribute(gemm_kernel, cudaFuncAttributeMaxDynamicSharedMemorySize, SMEM_BYTES);

    k_wconv<<<(NN * (size_t)KK) / (8 * 256), 256>>>((const int4*)w32);
    k_xconv<<<(MM * (size_t)KK) / (4 * 256), 256>>>((const float4*)x);
    gemm_kernel<<<(MM / BM) * (NN / BN), NTHREADS, SMEM_BYTES>>>(scale, bias, out);
}